// round 9
// baseline (speedup 1.0000x reference)
#include <cuda_runtime.h>

// CountVectorizer == per-row bincount over vocab followed by counts @ W + b.
//   out[b, :] = bias + sum_t W[token_ids[b, t], :]   (embedding gather-sum)
//
// Ledger: R1 (512B float4 gathers, 1 wave) 12.4us; R6 (256B float2, 1 wave)
// 11.33us; R8 (128B float1 but TWO waves: 524k threads > 303k resident)
// 14.4us. Same bytes each time -> the live variables are (a) ONE resident
// wave (<= ~9472 warps) and (b) gather request width: narrower request =
// fewer within-LDG L1tex wavefront replays (2.07 cyc/wf within vs 1.0
// cross). This round: 128B (LDG.32) gathers at exactly R6's residency.
// grid 2048 x 128 thr: CTA = (row, d-half); 4 warps = 2 d-quarters x 2
// token streams; each warp does 100 one-line gathers. LSU floor ~5.2us
// chip-wide stays under memory time.

#define CV_BATCH  1024
#define CV_SEQ    200
#define CV_D      128               // d_model
#define CV_QF     32                // floats per quarter (128 B line)

__global__ __launch_bounds__(128)
void count_vectorizer_kernel(const int* __restrict__ token_ids,
                             const float* __restrict__ W,
                             const float* __restrict__ bias,
                             float* __restrict__ out)
{
    __shared__ int   s_ids[CV_SEQ];
    __shared__ float s_acc[4][CV_QF];

    const int b = blockIdx.x >> 1;        // batch row
    const int h = blockIdx.x & 1;         // d-half (64 floats)

    // Stage this row's 200 token ids (2 coalesced rounds of 128).
    for (int i = threadIdx.x; i < CV_SEQ; i += 128)
        s_ids[i] = token_ids[b * CV_SEQ + i];
    __syncthreads();

    const int lane = threadIdx.x & 31;
    const int w    = threadIdx.x >> 5;    // warp 0..3
    const int q    = w & 1;               // d-quarter within the half
    const int s    = w >> 1;              // token stream 0/1 (100 tokens each)
    const int dcol = h * 64 + q * CV_QF + lane;   // float column in full row

    float acc = 0.f;

    // 100 gathers per warp, each one contiguous 128B line (1 L1tex wavefront).
    #pragma unroll 10
    for (int t = s; t < CV_SEQ; t += 2)
        acc += __ldg(&W[s_ids[t] * CV_D + dcol]);

    s_acc[w][lane] = acc;
    __syncthreads();

    // Threads 0..63: fold the 2 stream partials per quarter, add bias, store.
    if (threadIdx.x < 64) {
        const int q2 = threadIdx.x >> 5;          // quarter
        const int ln = threadIdx.x & 31;
        const int d  = h * 64 + threadIdx.x;      // float column in full row
        float a = s_acc[q2][ln] + s_acc[q2 + 2][ln] + __ldg(&bias[d]);
        out[b * CV_D + d] = a;
    }
}

extern "C" void kernel_launch(void* const* d_in, const int* in_sizes, int n_in,
                              void* d_out, int out_size)
{
    const int*   token_ids = (const int*)d_in[0];      // [1024, 200] int32
    const float* W         = (const float*)d_in[1];    // [100000, 128] f32
    const float* bias      = (const float*)d_in[2];    // [128] f32
    float*       out       = (float*)d_out;            // [1024, 128] f32

    (void)in_sizes; (void)n_in; (void)out_size;

    count_vectorizer_kernel<<<2 * CV_BATCH, 128>>>(token_ids, W, bias, out);
}

// round 10
// speedup vs baseline: 1.1693x; 1.1693x over previous
#include <cuda_runtime.h>

// CountVectorizer == per-row bincount over vocab followed by counts @ W + b.
//   out[b, :] = bias + sum_t W[token_ids[b, t], :]   (embedding gather-sum)
//
// Ledger (same total gather bytes each time):
//   float4 gathers, 205k LDG (R1):  12.4 us
//   float2 gathers, 410k LDG (R6):  11.33 us   <- champion shape
//   float1 gathers, 819k LDG (R8/R9): 14.37 us (one wave or two - identical)
// -> request width has an interior optimum at float2: LDG.32 doubles the
//    dynamic instruction stream (LDG+FADD+LDS) and per-LDG tag work and
//    loses more than it saves in within-LDG replays. Warm delivery at R6 is
//    9.3 TB/s, plausibly AT the NAT-clock LTS cap.
// This round: R6 exact shape + the only untested cheap lever - unroll 10
// with dual accumulators (break FADD RAW between load batches), reg-capped
// (launch_bounds 128,14 -> <=36 regs) so residency cannot regress, and a
// 64-wide reduction tail.

#define CV_BATCH  1024
#define CV_SEQ    200
#define CV_D      128               // d_model
#define CV_D2     (CV_D / 2)        // 64 float2 per full row
#define CV_HALF2  32                // float2 per half row (256 B)
#define CV_WARPS  4

__global__ __launch_bounds__(128, 14)
void count_vectorizer_kernel(const int* __restrict__ token_ids,
                             const float2* __restrict__ W2,
                             const float* __restrict__ bias,
                             float* __restrict__ out)
{
    __shared__ int   s_ids[CV_SEQ];
    __shared__ float s_accx[CV_WARPS][CV_HALF2];
    __shared__ float s_accy[CV_WARPS][CV_HALF2];

    const int b = blockIdx.x >> 1;        // batch row
    const int h = blockIdx.x & 1;         // d-half (0: floats 0..63, 1: 64..127)

    for (int i = threadIdx.x; i < CV_SEQ; i += 128)
        s_ids[i] = token_ids[b * CV_SEQ + i];
    __syncthreads();

    const int lane = threadIdx.x & 31;    // float2 slice within the half-row
    const int w    = threadIdx.x >> 5;    // warp id 0..3 (token stream)
    const int dcol = h * CV_HALF2 + lane; // float2 column in the full row

    // Dual accumulators: consecutive unrolled iterations hit different accs,
    // so batch k+1's loads aren't serialized behind batch k's adds.
    float2 a0 = make_float2(0.f, 0.f);
    float2 a1 = make_float2(0.f, 0.f);

    // 50 tokens per warp, unroll 10 -> ~10 LDG.64 in flight per thread.
    #pragma unroll 10
    for (int k = 0; k < 50; k += 2) {
        const float2 v0 = __ldg(&W2[s_ids[w + CV_WARPS * k]       * CV_D2 + dcol]);
        const float2 v1 = __ldg(&W2[s_ids[w + CV_WARPS * (k + 1)] * CV_D2 + dcol]);
        a0.x += v0.x; a0.y += v0.y;
        a1.x += v1.x; a1.y += v1.y;
    }

    s_accx[w][lane] = a0.x + a1.x;
    s_accy[w][lane] = a0.y + a1.y;
    __syncthreads();

    // 64 threads: each owns one float of the half-row; fold 4 partials + bias.
    if (threadIdx.x < 64) {
        const int ln = threadIdx.x >> 1;          // float2 column 0..31
        const int c  = threadIdx.x & 1;           // x / y component
        const int d  = h * 64 + ln * 2 + c;       // float column in full row
        float s = __ldg(&bias[d]);
        if (c == 0) {
            #pragma unroll
            for (int g = 0; g < CV_WARPS; g++) s += s_accx[g][ln];
        } else {
            #pragma unroll
            for (int g = 0; g < CV_WARPS; g++) s += s_accy[g][ln];
        }
        out[b * CV_D + d] = s;
    }
}

extern "C" void kernel_launch(void* const* d_in, const int* in_sizes, int n_in,
                              void* d_out, int out_size)
{
    const int*   token_ids = (const int*)d_in[0];      // [1024, 200] int32
    const float* W         = (const float*)d_in[1];    // [100000, 128] f32
    const float* bias      = (const float*)d_in[2];    // [128] f32
    float*       out       = (float*)d_out;            // [1024, 128] f32

    (void)in_sizes; (void)n_in; (void)out_size;

    count_vectorizer_kernel<<<2 * CV_BATCH, 128>>>(
        token_ids,
        reinterpret_cast<const float2*>(W),
        bias,
        out);
}

// round 11
// speedup vs baseline: 1.2720x; 1.0878x over previous
#include <cuda_runtime.h>

// CountVectorizer == per-row bincount over vocab followed by counts @ W + b.
//   out[b, :] = bias + sum_t W[token_ids[b, t], :]   (embedding gather-sum)
//
// Ledger (same total gather bytes, one resident wave unless noted):
//   float4 unroll5  (R1) : 12.4 us   (~20 front-batched wf/warp-batch)
//   float2 unroll5  (R6) : 11.33 us  (~10 wf)  <- champion
//   float2 unroll10 (R10): 12.29 us  (~20 wf)
//   float1          (R8/9): 14.37 us (2x dynamic instr count)
// -> completion spread grows with front-batched L1tex wavefront depth
//    (oe*MLP_p1 spread model); latency is already hidden at unroll 5, so
//    extra MLP only deepens cross-CTA queue contention. R6 shape is the
//    local optimum in (width x unroll x residency).
// This round: R6 verbatim, with ld.global.cg (L1-bypass) instead of
// ld.global.nc on the W gathers - gathered lines have zero L1 reuse, so
// skipping L1 allocation trims per-wavefront tag/eviction work.

#define CV_BATCH  1024
#define CV_SEQ    200
#define CV_D      128               // d_model
#define CV_D2     (CV_D / 2)        // 64 float2 per full row
#define CV_HALF2  32                // float2 per half row (256 B)
#define CV_WARPS  4

__global__ __launch_bounds__(128)
void count_vectorizer_kernel(const int* __restrict__ token_ids,
                             const float2* __restrict__ W2,
                             const float2* __restrict__ bias2,
                             float2* __restrict__ out2)
{
    __shared__ int    s_ids[CV_SEQ];
    __shared__ float2 s_acc[CV_WARPS][CV_HALF2];

    const int b = blockIdx.x >> 1;        // batch row
    const int h = blockIdx.x & 1;         // d-half (0: floats 0..63, 1: 64..127)

    // Stage this row's 200 token ids (2 coalesced rounds of 128).
    for (int i = threadIdx.x; i < CV_SEQ; i += 128)
        s_ids[i] = token_ids[b * CV_SEQ + i];
    __syncthreads();

    const int lane = threadIdx.x & 31;    // float2 slice within the half-row
    const int w    = threadIdx.x >> 5;    // warp id 0..3 (token stream)
    const int dcol = h * CV_HALF2 + lane; // float2 column in the full row

    float2 acc = make_float2(0.f, 0.f);

    // 50 gathers per warp; unroll 5 = proven sweet spot (~5 LDG.64 in flight).
    // L1-bypass (.cg): random-gathered lines are never reused in L1.
    #pragma unroll 5
    for (int t = w; t < CV_SEQ; t += CV_WARPS) {
        const float2 v = __ldcg(&W2[s_ids[t] * CV_D2 + dcol]);
        acc.x += v.x; acc.y += v.y;
    }

    s_acc[w][lane] = acc;
    __syncthreads();

    // Warp 0 folds the 4 partials, adds bias, stores the 256B half-row.
    if (w == 0) {
        float2 a = s_acc[0][lane];
        #pragma unroll
        for (int g = 1; g < CV_WARPS; g++) {
            const float2 v = s_acc[g][lane];
            a.x += v.x; a.y += v.y;
        }
        const float2 bb = __ldg(&bias2[dcol]);
        a.x += bb.x; a.y += bb.y;
        out2[b * CV_D2 + dcol] = a;
    }
}

extern "C" void kernel_launch(void* const* d_in, const int* in_sizes, int n_in,
                              void* d_out, int out_size)
{
    const int*   token_ids = (const int*)d_in[0];      // [1024, 200] int32
    const float* W         = (const float*)d_in[1];    // [100000, 128] f32
    const float* bias      = (const float*)d_in[2];    // [128] f32
    float*       out       = (float*)d_out;            // [1024, 128] f32

    (void)in_sizes; (void)n_in; (void)out_size;

    count_vectorizer_kernel<<<2 * CV_BATCH, 128>>>(
        token_ids,
        reinterpret_cast<const float2*>(W),
        reinterpret_cast<const float2*>(bias),
        reinterpret_cast<float2*>(out));
}